// round 15
// baseline (speedup 1.0000x reference)
#include <cuda_runtime.h>
#include <cuda_fp16.h>
#include <math.h>
#include <float.h>

// Problem constants
#define NTOK   65536
#define DIM    64
#define KCODES 1024

// Certified margin (validated in R7/R12): mg = MGK * sum|x| + MGS
#define MGK   1.47e-4f
#define MGS   3e-4f

// Output layout (float32 concatenation of the reference tuple)
#define OFF_Q    0
#define OFF_CM   4194304
#define OFF_CB   4194305
#define OFF_P    4194306
#define OFF_E    4194307
#define OFF_CNT  (OFF_E + KCODES*DIM)
#define OFF_W    (OFF_CNT + KCODES)
#define OFF_USE  (OFF_W + KCODES*DIM)

// Scratch (static device globals; no cudaMalloc allowed)
__device__ float          g_counts[KCODES];
__device__ float          g_dw[KCODES * DIM];
__device__ float          g_enorm[KCODES];
__device__ unsigned short g_staged[KCODES * 64];   // fp16 fragment-permuted B
__device__ int            g_idx[NTOK];
__device__ unsigned       g_flag2[NTOK];           // (token<<16) | chunkmask
__device__ int            g_nflag2;
__device__ double         g_loss;

#define MMA_F16(d0,d1,d2,d3,a0,a1,a2,a3,b0,b1)                                \
    asm("mma.sync.aligned.m16n8k16.row.col.f32.f16.f16.f32 "                  \
        "{%0,%1,%2,%3}, {%4,%5,%6,%7}, {%8,%9}, {%0,%1,%2,%3};"               \
        : "+f"(d0), "+f"(d1), "+f"(d2), "+f"(d3)                              \
        : "r"(a0), "r"(a1), "r"(a2), "r"(a3), "r"(b0), "r"(b1))

__device__ __forceinline__ unsigned pack_h2(float lo, float hi) {
    __half2 h = __floats2half2_rn(lo, hi);
    return *(unsigned*)&h;
}
__device__ __forceinline__ unsigned fkey(float f) {
    unsigned u = __float_as_uint(f);
    return (u & 0x80000000u) ? ~u : (u | 0x80000000u);
}

// ---------------------------------------------------------------------------
// Kernel 0: zero scratch; enorm; fp16 fragment-permuted B (R7-validated).
// ---------------------------------------------------------------------------
__global__ void setup_kernel(const float* __restrict__ emb) {
    int gtid = blockIdx.x * 256 + threadIdx.x;      // 0..65535
    g_dw[gtid] = 0.0f;
    if (gtid < KCODES) g_counts[gtid] = 0.0f;
    if (gtid == 0) { g_loss = 0.0; g_nflag2 = 0; }

    int c = gtid >> 6;      // code
    int d = gtid & 63;      // dim
    float e = __ldg(emb + gtid);
    __half hb = __float2half_rn(e);

    int p   = d >> 1;
    int ks  = p >> 3;
    int pos = p & 7;
    int w   = (pos < 4) ? 2 * (ks * 4 + pos) : 2 * (ks * 4 + pos - 4) + 1;
    g_staged[c * 64 + w * 2 + (d & 1)] = __half_as_ushort(hb);

    // enorm (identical reduction tree to the passing kernels)
    if (blockIdx.x < 64) {
        int code = blockIdx.x * 16 + (threadIdx.x >> 4);
        int sub  = threadIdx.x & 15;
        float4 v = __ldg(((const float4*)(emb + (size_t)code * DIM)) + sub);
        float s = __fmul_rn(v.x, v.x);
        s = __fmaf_rn(v.y, v.y, s);
        s = __fmaf_rn(v.z, v.z, s);
        s = __fmaf_rn(v.w, v.w, s);
        #pragma unroll
        for (int off = 8; off > 0; off >>= 1)
            s = __fadd_rn(s, __shfl_down_sync(0xffffffffu, s, off));
        if (sub == 0) g_enorm[code] = s;
    }
}

// ---------------------------------------------------------------------------
// Kernel 1: fp16 1-split MMA assign + per-chunk min (R12/R13-proven, frozen).
// ---------------------------------------------------------------------------
#define ROWB 160              // B smem row stride bytes (128 + 32)

__global__ __launch_bounds__(256, 2)
void mma_assign_kernel(const float* __restrict__ x) {
    __shared__ __align__(16) unsigned char sbuf[2][64 * ROWB];  // 20 KB
    __shared__ float sEN[KCODES];                                // 4 KB
    __shared__ float scmin[256][16];                             // 16 KB

    int tid  = threadIdx.x;
    int lane = tid & 31;
    int wid  = tid >> 5;
    int r    = lane >> 2;
    int q    = lane & 3;
    int warptok = blockIdx.x * 256 + wid * 32;

    unsigned sb[2];
    asm("{ .reg .u64 t; cvta.to.shared.u64 t, %1; cvt.u32.u64 %0, t; }"
        : "=r"(sb[0]) : "l"(sbuf[0]));
    asm("{ .reg .u64 t; cvta.to.shared.u64 t, %1; cvt.u32.u64 %0, t; }"
        : "=r"(sb[1]) : "l"(sbuf[1]));

    // prefetch chunk 0 (64 codes x 128 B = 512 16B pieces)
    {
        const float4* src = (const float4*)g_staged;
        #pragma unroll
        for (int k2 = 0; k2 < 2; k2++) {
            int p = tid + k2 * 256;
            asm volatile("cp.async.cg.shared.global [%0], [%1], 16;"
                :: "r"(sb[0] + (p >> 3) * ROWB + (p & 7) * 16), "l"(src + p)
                : "memory");
        }
        asm volatile("cp.async.commit_group;" ::: "memory");
    }

    // en table
    #pragma unroll
    for (int i = 0; i < 4; i++) sEN[i * 256 + tid] = g_enorm[i * 256 + tid];

    // ---- A fragments (fp16) + per-row-group |x| sums ----
    unsigned ahi[4][4][2];
    float sabs[4] = {0, 0, 0, 0};
    #pragma unroll
    for (int g = 0; g < 4; g++) {
        const float* xr = x + (size_t)(warptok + g * 8 + r) * DIM + 2 * q;
        #pragma unroll
        for (int ks = 0; ks < 4; ks++) {
            float2 v0 = __ldg((const float2*)(xr + 16 * ks));
            float2 v1 = __ldg((const float2*)(xr + 16 * ks + 8));
            ahi[g][ks][0] = pack_h2(v0.x, v0.y);
            ahi[g][ks][1] = pack_h2(v1.x, v1.y);
            sabs[g] += ((fabsf(v0.x) + fabsf(v0.y)) +
                        (fabsf(v1.x) + fabsf(v1.y)));
        }
    }
    float mg[4];
    #pragma unroll
    for (int g = 0; g < 4; g++) {
        float s = sabs[g];
        s += __shfl_xor_sync(0xffffffffu, s, 1);
        s += __shfl_xor_sync(0xffffffffu, s, 2);
        mg[g] = __fmaf_rn(s, MGK, MGS);
    }
    __syncthreads();

    float b1v[4] = {FLT_MAX, FLT_MAX, FLT_MAX, FLT_MAX};
    float b2v[4] = {FLT_MAX, FLT_MAX, FLT_MAX, FLT_MAX};
    int   i1v[4] = {0, 0, 0, 0};

    for (int c = 0; c < 16; c++) {
        if (c + 1 < 16) {
            const float4* src = ((const float4*)g_staged) + (c + 1) * 512;
            unsigned dst = sb[(c + 1) & 1];
            #pragma unroll
            for (int k2 = 0; k2 < 2; k2++) {
                int p = tid + k2 * 256;
                asm volatile("cp.async.cg.shared.global [%0], [%1], 16;"
                    :: "r"(dst + (p >> 3) * ROWB + (p & 7) * 16), "l"(src + p)
                    : "memory");
            }
            asm volatile("cp.async.commit_group;" ::: "memory");
            asm volatile("cp.async.wait_group 1;" ::: "memory");
        } else {
            asm volatile("cp.async.wait_group 0;" ::: "memory");
        }
        __syncthreads();

        const unsigned char* buf = sbuf[c & 1];
        int cbase = c * 64;
        float cm[4] = {FLT_MAX, FLT_MAX, FLT_MAX, FLT_MAX};

        #pragma unroll 2
        for (int nt = 0; nt < 8; nt++) {
            const unsigned char* row = buf + (nt * 8 + r) * ROWB + q * 8;
            float a00 = 0, a01 = 0, a02 = 0, a03 = 0;   // tile0 chain A
            float b00 = 0, b01 = 0, b02 = 0, b03 = 0;   // tile0 chain B
            float a10 = 0, a11 = 0, a12 = 0, a13 = 0;   // tile1 chain A
            float b10 = 0, b11 = 0, b12 = 0, b13 = 0;   // tile1 chain B
            #pragma unroll
            for (int ks = 0; ks < 2; ks++) {
                unsigned long long bwA =
                    *(const unsigned long long*)(row + ks * 32);
                unsigned long long bwB =
                    *(const unsigned long long*)(row + (ks + 2) * 32);
                unsigned bA0 = (unsigned)bwA, bA1 = (unsigned)(bwA >> 32);
                unsigned bB0 = (unsigned)bwB, bB1 = (unsigned)(bwB >> 32);
                MMA_F16(a00, a01, a02, a03,
                        ahi[0][ks][0], ahi[1][ks][0],
                        ahi[0][ks][1], ahi[1][ks][1], bA0, bA1);
                MMA_F16(b00, b01, b02, b03,
                        ahi[0][ks + 2][0], ahi[1][ks + 2][0],
                        ahi[0][ks + 2][1], ahi[1][ks + 2][1], bB0, bB1);
                MMA_F16(a10, a11, a12, a13,
                        ahi[2][ks][0], ahi[3][ks][0],
                        ahi[2][ks][1], ahi[3][ks][1], bA0, bA1);
                MMA_F16(b10, b11, b12, b13,
                        ahi[2][ks + 2][0], ahi[3][ks + 2][0],
                        ahi[2][ks + 2][1], ahi[3][ks + 2][1], bB0, bB1);
            }
            int c0 = cbase + nt * 8 + 2 * q;
            float en0 = sEN[c0], en1 = sEN[c0 + 1];
            float k00 = __fmaf_rn(-2.0f, __fadd_rn(a00, b00), en0);
            float k01 = __fmaf_rn(-2.0f, __fadd_rn(a01, b01), en1);
            float k02 = __fmaf_rn(-2.0f, __fadd_rn(a02, b02), en0);
            float k03 = __fmaf_rn(-2.0f, __fadd_rn(a03, b03), en1);
            float k10 = __fmaf_rn(-2.0f, __fadd_rn(a10, b10), en0);
            float k11 = __fmaf_rn(-2.0f, __fadd_rn(a11, b11), en1);
            float k12 = __fmaf_rn(-2.0f, __fadd_rn(a12, b12), en0);
            float k13 = __fmaf_rn(-2.0f, __fadd_rn(a13, b13), en1);

            cm[0] = fminf(cm[0], fminf(k00, k01));
            cm[1] = fminf(cm[1], fminf(k02, k03));
            cm[2] = fminf(cm[2], fminf(k10, k11));
            cm[3] = fminf(cm[3], fminf(k12, k13));

            if (k00 < b1v[0]) { b2v[0]=b1v[0]; b1v[0]=k00; i1v[0]=c0; }
            else if (k00 < b2v[0]) b2v[0]=k00;
            if (k01 < b1v[0]) { b2v[0]=b1v[0]; b1v[0]=k01; i1v[0]=c0+1; }
            else if (k01 < b2v[0]) b2v[0]=k01;
            if (k02 < b1v[1]) { b2v[1]=b1v[1]; b1v[1]=k02; i1v[1]=c0; }
            else if (k02 < b2v[1]) b2v[1]=k02;
            if (k03 < b1v[1]) { b2v[1]=b1v[1]; b1v[1]=k03; i1v[1]=c0+1; }
            else if (k03 < b2v[1]) b2v[1]=k03;
            if (k10 < b1v[2]) { b2v[2]=b1v[2]; b1v[2]=k10; i1v[2]=c0; }
            else if (k10 < b2v[2]) b2v[2]=k10;
            if (k11 < b1v[2]) { b2v[2]=b1v[2]; b1v[2]=k11; i1v[2]=c0+1; }
            else if (k11 < b2v[2]) b2v[2]=k11;
            if (k12 < b1v[3]) { b2v[3]=b1v[3]; b1v[3]=k12; i1v[3]=c0; }
            else if (k12 < b2v[3]) b2v[3]=k12;
            if (k13 < b1v[3]) { b2v[3]=b1v[3]; b1v[3]=k13; i1v[3]=c0+1; }
            else if (k13 < b2v[3]) b2v[3]=k13;
        }

        #pragma unroll
        for (int s = 0; s < 4; s++) {
            cm[s] = fminf(cm[s], __shfl_xor_sync(0xffffffffu, cm[s], 1));
            cm[s] = fminf(cm[s], __shfl_xor_sync(0xffffffffu, cm[s], 2));
        }
        if (q == 0) {
            #pragma unroll
            for (int s = 0; s < 4; s++)
                scmin[wid * 32 + s * 8 + r][c] = cm[s];
        }
        __syncthreads();
    }

    // ---- merge best1/best2 across the 4 q-lanes of each row group ----
    #pragma unroll
    for (int s = 0; s < 4; s++) {
        #pragma unroll
        for (int m = 1; m <= 2; m <<= 1) {
            float ob1 = __shfl_xor_sync(0xffffffffu, b1v[s], m);
            int   oi1 = __shfl_xor_sync(0xffffffffu, i1v[s], m);
            float ob2 = __shfl_xor_sync(0xffffffffu, b2v[s], m);
            bool take = (ob1 < b1v[s]) || (ob1 == b1v[s] && oi1 < i1v[s]);
            float nb2 = take ? fminf(b1v[s], ob2) : fminf(b2v[s], ob1);
            if (take) { b1v[s] = ob1; i1v[s] = oi1; }
            b2v[s] = nb2;
        }
    }

    if (q == 0) {
        #pragma unroll
        for (int s = 0; s < 4; s++) {
            int lt    = wid * 32 + s * 8 + r;
            int token = blockIdx.x * 256 + lt;
            g_idx[token] = i1v[s];
            float th = __fadd_rn(b1v[s], mg[s]);
            if (b2v[s] <= th) {
                unsigned mask = 0;
                #pragma unroll
                for (int c = 0; c < 16; c++)
                    if (scmin[lt][c] <= th) mask |= (1u << c);
                int p = atomicAdd(&g_nflag2, 1);
                g_flag2[p] = ((unsigned)token << 16) | mask;
            }
        }
    }
}

// ---------------------------------------------------------------------------
// Kernel 2: chunk-targeted exact re-rank (warp per flagged token; frozen).
// ---------------------------------------------------------------------------
__global__ __launch_bounds__(256)
void refine_kernel(const float* __restrict__ x, const float* __restrict__ emb) {
    int nf   = g_nflag2;
    int lane = threadIdx.x & 31;
    int gw   = (blockIdx.x * 256 + threadIdx.x) >> 5;
    int nw   = gridDim.x * 8;

    for (int f = gw; f < nf; f += nw) {
        unsigned e = g_flag2[f];
        int token  = (int)(e >> 16);
        unsigned mask = e & 0xFFFFu;
        const float* xr = x + (size_t)token * DIM;

        float sx[DIM];
        float xn = 0.0f;
        #pragma unroll
        for (int d = 0; d < DIM; d++) {
            sx[d] = __ldg(xr + d);
            xn = __fmaf_rn(sx[d], sx[d], xn);
        }

        unsigned long long bkey = 0xFFFFFFFFFFFFFFFFull;
        while (mask) {
            int c = __ffs(mask) - 1;
            mask &= mask - 1;
            #pragma unroll
            for (int half = 0; half < 2; half++) {
                int code = c * 64 + half * 32 + lane;
                const float4* er = (const float4*)(emb + (size_t)code * DIM);
                float s[8] = {0, 0, 0, 0, 0, 0, 0, 0};
                #pragma unroll
                for (int jj = 0; jj < 8; jj++) {
                    float4 e0 = __ldg(er + 2 * jj);
                    float4 e1 = __ldg(er + 2 * jj + 1);
                    s[0] = __fmaf_rn(sx[jj * 8 + 0], e0.x, s[0]);
                    s[1] = __fmaf_rn(sx[jj * 8 + 1], e0.y, s[1]);
                    s[2] = __fmaf_rn(sx[jj * 8 + 2], e0.z, s[2]);
                    s[3] = __fmaf_rn(sx[jj * 8 + 3], e0.w, s[3]);
                    s[4] = __fmaf_rn(sx[jj * 8 + 4], e1.x, s[4]);
                    s[5] = __fmaf_rn(sx[jj * 8 + 5], e1.y, s[5]);
                    s[6] = __fmaf_rn(sx[jj * 8 + 6], e1.z, s[6]);
                    s[7] = __fmaf_rn(sx[jj * 8 + 7], e1.w, s[7]);
                }
                float lo  = __fadd_rn(__fadd_rn(s[0], s[2]), __fadd_rn(s[4], s[6]));
                float hi  = __fadd_rn(__fadd_rn(s[1], s[3]), __fadd_rn(s[5], s[7]));
                float dot = __fadd_rn(lo, hi);
                float d2  = __fadd_rn(__fmaf_rn(-2.0f, dot, xn), g_enorm[code]);
                unsigned long long key =
                    ((unsigned long long)fkey(d2) << 32) | (unsigned)code;
                if (key < bkey) bkey = key;
            }
        }
        #pragma unroll
        for (int off = 16; off > 0; off >>= 1) {
            unsigned long long o = __shfl_xor_sync(0xffffffffu, bkey, off);
            if (o < bkey) bkey = o;
        }
        if (lane == 0) g_idx[token] = (int)(bkey & 0xFFFFFFFFull);
    }
}

// ---------------------------------------------------------------------------
// Kernel 3: epilogue — 8 threads/token (R13-measured-best); v4 REDG;
//           streaming Q stores; 1 loss atomic per CTA.
// ---------------------------------------------------------------------------
__global__ __launch_bounds__(256)
void epilogue_kernel(const float* __restrict__ x,
                     const float* __restrict__ emb,
                     float* __restrict__ out) {
    __shared__ double sred[8];
    int gid   = blockIdx.x * 256 + threadIdx.x;
    int token = gid >> 3;
    int part  = gid & 7;
    int bi = g_idx[token];

    const float4* xrow = (const float4*)(x + ((size_t)token << 6)) + part * 2;
    const float4* erow = (const float4*)(emb + ((size_t)bi << 6)) + part * 2;
    float4* orow = (float4*)(out + OFF_Q + ((size_t)token << 6)) + part * 2;
    float* dwrow = g_dw + ((size_t)bi << 6) + part * 8;

    float lsum = 0.0f;
    #pragma unroll
    for (int j = 0; j < 2; j++) {
        float4 xv = __ldg(xrow + j);
        float4 q  = __ldg(erow + j);
        float4 o;
        o.x = __fadd_rn(xv.x, __fadd_rn(q.x, -xv.x));
        o.y = __fadd_rn(xv.y, __fadd_rn(q.y, -xv.y));
        o.z = __fadd_rn(xv.z, __fadd_rn(q.z, -xv.z));
        o.w = __fadd_rn(xv.w, __fadd_rn(q.w, -xv.w));
        __stcs(orow + j, o);                     // streaming: bypass L1
        float d0 = __fadd_rn(xv.x, -q.x);
        float d1 = __fadd_rn(xv.y, -q.y);
        float d2 = __fadd_rn(xv.z, -q.z);
        float d3 = __fadd_rn(xv.w, -q.w);
        lsum = __fmaf_rn(d0, d0, lsum);
        lsum = __fmaf_rn(d1, d1, lsum);
        lsum = __fmaf_rn(d2, d2, lsum);
        lsum = __fmaf_rn(d3, d3, lsum);
        asm volatile("red.global.add.v4.f32 [%0], {%1, %2, %3, %4};"
                     :: "l"(dwrow + 4 * j),
                        "f"(xv.x), "f"(xv.y), "f"(xv.z), "f"(xv.w)
                     : "memory");
    }
    if (part == 0) atomicAdd(&g_counts[bi], 1.0f);

    double dl = (double)lsum;
    #pragma unroll
    for (int off = 16; off > 0; off >>= 1)
        dl += __shfl_down_sync(0xffffffffu, dl, off);
    if ((threadIdx.x & 31) == 0) sred[threadIdx.x >> 5] = dl;
    __syncthreads();
    if (threadIdx.x == 0) {
        double t = ((sred[0] + sred[1]) + (sred[2] + sred[3]))
                 + ((sred[4] + sred[5]) + (sred[6] + sred[7]));
        atomicAdd(&g_loss, t);
    }
}

// ---------------------------------------------------------------------------
// Kernel 4: merged finalize + ema (R14-validated). Grid 64 x 1024 threads.
// ---------------------------------------------------------------------------
__global__ void finalize_ema_kernel(const float* __restrict__ ema_count,
                                    const float* __restrict__ ema_weight,
                                    const float* __restrict__ usage,
                                    float* __restrict__ out) {
    __shared__ float red_n[1024];
    __shared__ float red_s[1024];
    int t = threadIdx.x;

    float c   = g_counts[t];
    float raw = __fadd_rn(__fmul_rn(0.999f, ema_count[t]), __fmul_rn(0.001f, c));

    float p   = c * (1.0f / 65536.0f);
    float ent = __fmul_rn(p, logf(__fadd_rn(p, 1e-10f)));

    red_n[t] = raw;
    red_s[t] = ent;
    __syncthreads();
    for (int s = 512; s > 0; s >>= 1) {
        if (t < s) {
            red_n[t] = __fadd_rn(red_n[t], red_n[t + s]);
            red_s[t] = __fadd_rn(red_s[t], red_s[t + s]);
        }
        __syncthreads();
    }
    float n    = red_n[0];
    float ssum = red_s[0];

    // ---- ema slice (codes blockIdx.x*16 .. +15) ----
    int idx  = blockIdx.x * 1024 + t;
    int code = idx >> 6;
    float craw = __fadd_rn(__fmul_rn(0.999f, __ldg(ema_count + code)),
                           __fmul_rn(0.001f, g_counts[code]));
    float cncnt = __fmul_rn(__fdiv_rn(__fadd_rn(craw, 1e-5f),
                                      __fadd_rn(n, 0.01024f)), n);
    float nw = __fadd_rn(__fmul_rn(0.999f, __ldg(ema_weight + idx)),
                         __fmul_rn(0.001f, g_dw[idx]));
    out[OFF_W + idx] = nw;
    out[OFF_E + idx] = __fdiv_rn(nw, cncnt);

    // ---- CTA 0: counts / usage / scalars ----
    if (blockIdx.x == 0) {
        float ncnt = __fmul_rn(__fdiv_rn(__fadd_rn(raw, 1e-5f),
                                         __fadd_rn(n, 0.01024f)), n);
        out[OFF_CNT + t] = ncnt;
        out[OFF_USE + t] = __fmul_rn(__fadd_rn(__ldg(usage + t),
                                               (c > 0.0f) ? 1.0f : 0.0f), 0.5f);
        if (t == 0) {
            float ml = (float)(g_loss * (1.0 / 4194304.0));
            out[OFF_CB] = ml;
            out[OFF_CM] = 0.25f * ml;
            out[OFF_P]  = expf(-ssum);
        }
    }
}

// ---------------------------------------------------------------------------
extern "C" void kernel_launch(void* const* d_in, const int* in_sizes, int n_in,
                              void* d_out, int out_size) {
    const float* x          = (const float*)d_in[0];
    const float* emb        = (const float*)d_in[1];
    const float* ema_count  = (const float*)d_in[2];
    const float* ema_weight = (const float*)d_in[3];
    const float* usage      = (const float*)d_in[4];
    float* out = (float*)d_out;

    setup_kernel<<<256, 256>>>(emb);
    mma_assign_kernel<<<NTOK / 256, 256>>>(x);
    refine_kernel<<<512, 256>>>(x, emb);
    epilogue_kernel<<<NTOK * 8 / 256, 256>>>(x, emb, out);
    finalize_ema_kernel<<<64, 1024>>>(ema_count, ema_weight, usage, out);
}

// round 16
// speedup vs baseline: 1.0324x; 1.0324x over previous
#include <cuda_runtime.h>
#include <cuda_fp16.h>
#include <math.h>
#include <float.h>

// Problem constants
#define NTOK   65536
#define DIM    64
#define KCODES 1024

// Certified margin (validated in R7/R12): mg = MGK * sum|x| + MGS
#define MGK   1.47e-4f
#define MGS   3e-4f

// Output layout (float32 concatenation of the reference tuple)
#define OFF_Q    0
#define OFF_CM   4194304
#define OFF_CB   4194305
#define OFF_P    4194306
#define OFF_E    4194307
#define OFF_CNT  (OFF_E + KCODES*DIM)
#define OFF_W    (OFF_CNT + KCODES)
#define OFF_USE  (OFF_W + KCODES*DIM)

// Scratch (static device globals; no cudaMalloc allowed)
__device__ float          g_counts[KCODES];
__device__ float          g_dw[KCODES * DIM];
__device__ float          g_enorm[KCODES];
__device__ unsigned short g_staged[KCODES * 64];   // fp16 fragment-permuted B
__device__ int            g_idx[NTOK];
__device__ double         g_loss;

#define MMA_F16(d0,d1,d2,d3,a0,a1,a2,a3,b0,b1)                                \
    asm("mma.sync.aligned.m16n8k16.row.col.f32.f16.f16.f32 "                  \
        "{%0,%1,%2,%3}, {%4,%5,%6,%7}, {%8,%9}, {%0,%1,%2,%3};"               \
        : "+f"(d0), "+f"(d1), "+f"(d2), "+f"(d3)                              \
        : "r"(a0), "r"(a1), "r"(a2), "r"(a3), "r"(b0), "r"(b1))

__device__ __forceinline__ unsigned pack_h2(float lo, float hi) {
    __half2 h = __floats2half2_rn(lo, hi);
    return *(unsigned*)&h;
}
__device__ __forceinline__ unsigned fkey(float f) {
    unsigned u = __float_as_uint(f);
    return (u & 0x80000000u) ? ~u : (u | 0x80000000u);
}

// ---------------------------------------------------------------------------
// Kernel 0: zero scratch; enorm; fp16 fragment-permuted B (R7-validated).
// ---------------------------------------------------------------------------
__global__ void setup_kernel(const float* __restrict__ emb) {
    int gtid = blockIdx.x * 256 + threadIdx.x;      // 0..65535
    g_dw[gtid] = 0.0f;
    if (gtid < KCODES) g_counts[gtid] = 0.0f;
    if (gtid == 0) g_loss = 0.0;

    int c = gtid >> 6;      // code
    int d = gtid & 63;      // dim
    float e = __ldg(emb + gtid);
    __half hb = __float2half_rn(e);

    int p   = d >> 1;
    int ks  = p >> 3;
    int pos = p & 7;
    int w   = (pos < 4) ? 2 * (ks * 4 + pos) : 2 * (ks * 4 + pos - 4) + 1;
    g_staged[c * 64 + w * 2 + (d & 1)] = __half_as_ushort(hb);

    // enorm (identical reduction tree to the passing kernels)
    if (blockIdx.x < 64) {
        int code = blockIdx.x * 16 + (threadIdx.x >> 4);
        int sub  = threadIdx.x & 15;
        float4 v = __ldg(((const float4*)(emb + (size_t)code * DIM)) + sub);
        float s = __fmul_rn(v.x, v.x);
        s = __fmaf_rn(v.y, v.y, s);
        s = __fmaf_rn(v.z, v.z, s);
        s = __fmaf_rn(v.w, v.w, s);
        #pragma unroll
        for (int off = 8; off > 0; off >>= 1)
            s = __fadd_rn(s, __shfl_down_sync(0xffffffffu, s, off));
        if (sub == 0) g_enorm[code] = s;
    }
}

// ---------------------------------------------------------------------------
// Kernel 1: fp16 1-split MMA assign + per-chunk min (R12/R13-proven hot loop)
// + FUSED refine tail: CTA-local flag list, warp-per-token exact re-rank over
// masked chunks only (identical rounding tree to the validated refine kernel).
// ---------------------------------------------------------------------------
#define ROWB 160              // B smem row stride bytes (128 + 32)

__global__ __launch_bounds__(256, 2)
void mma_assign_kernel(const float* __restrict__ x,
                       const float* __restrict__ emb) {
    __shared__ __align__(16) unsigned char sbuf[2][64 * ROWB];  // 20 KB
    __shared__ float sEN[KCODES];                                // 4 KB
    __shared__ float scmin[256][16];                             // 16 KB
    __shared__ unsigned s_fl[256];                               // 1 KB
    __shared__ int s_nf;
    __shared__ float sxs[8][64];                                 // 2 KB

    int tid  = threadIdx.x;
    int lane = tid & 31;
    int wid  = tid >> 5;
    int r    = lane >> 2;
    int q    = lane & 3;
    int warptok = blockIdx.x * 256 + wid * 32;

    if (tid == 0) s_nf = 0;

    unsigned sb[2];
    asm("{ .reg .u64 t; cvta.to.shared.u64 t, %1; cvt.u32.u64 %0, t; }"
        : "=r"(sb[0]) : "l"(sbuf[0]));
    asm("{ .reg .u64 t; cvta.to.shared.u64 t, %1; cvt.u32.u64 %0, t; }"
        : "=r"(sb[1]) : "l"(sbuf[1]));

    // prefetch chunk 0 (64 codes x 128 B = 512 16B pieces)
    {
        const float4* src = (const float4*)g_staged;
        #pragma unroll
        for (int k2 = 0; k2 < 2; k2++) {
            int p = tid + k2 * 256;
            asm volatile("cp.async.cg.shared.global [%0], [%1], 16;"
                :: "r"(sb[0] + (p >> 3) * ROWB + (p & 7) * 16), "l"(src + p)
                : "memory");
        }
        asm volatile("cp.async.commit_group;" ::: "memory");
    }

    // en table
    #pragma unroll
    for (int i = 0; i < 4; i++) sEN[i * 256 + tid] = g_enorm[i * 256 + tid];

    // ---- A fragments (fp16) + per-row-group |x| sums ----
    unsigned ahi[4][4][2];
    float sabs[4] = {0, 0, 0, 0};
    #pragma unroll
    for (int g = 0; g < 4; g++) {
        const float* xr = x + (size_t)(warptok + g * 8 + r) * DIM + 2 * q;
        #pragma unroll
        for (int ks = 0; ks < 4; ks++) {
            float2 v0 = __ldg((const float2*)(xr + 16 * ks));
            float2 v1 = __ldg((const float2*)(xr + 16 * ks + 8));
            ahi[g][ks][0] = pack_h2(v0.x, v0.y);
            ahi[g][ks][1] = pack_h2(v1.x, v1.y);
            sabs[g] += ((fabsf(v0.x) + fabsf(v0.y)) +
                        (fabsf(v1.x) + fabsf(v1.y)));
        }
    }
    float mg[4];
    #pragma unroll
    for (int g = 0; g < 4; g++) {
        float s = sabs[g];
        s += __shfl_xor_sync(0xffffffffu, s, 1);
        s += __shfl_xor_sync(0xffffffffu, s, 2);
        mg[g] = __fmaf_rn(s, MGK, MGS);
    }
    __syncthreads();

    float b1v[4] = {FLT_MAX, FLT_MAX, FLT_MAX, FLT_MAX};
    float b2v[4] = {FLT_MAX, FLT_MAX, FLT_MAX, FLT_MAX};
    int   i1v[4] = {0, 0, 0, 0};

    for (int c = 0; c < 16; c++) {
        if (c + 1 < 16) {
            const float4* src = ((const float4*)g_staged) + (c + 1) * 512;
            unsigned dst = sb[(c + 1) & 1];
            #pragma unroll
            for (int k2 = 0; k2 < 2; k2++) {
                int p = tid + k2 * 256;
                asm volatile("cp.async.cg.shared.global [%0], [%1], 16;"
                    :: "r"(dst + (p >> 3) * ROWB + (p & 7) * 16), "l"(src + p)
                    : "memory");
            }
            asm volatile("cp.async.commit_group;" ::: "memory");
            asm volatile("cp.async.wait_group 1;" ::: "memory");
        } else {
            asm volatile("cp.async.wait_group 0;" ::: "memory");
        }
        __syncthreads();

        const unsigned char* buf = sbuf[c & 1];
        int cbase = c * 64;
        float cm[4] = {FLT_MAX, FLT_MAX, FLT_MAX, FLT_MAX};

        #pragma unroll 2
        for (int nt = 0; nt < 8; nt++) {
            const unsigned char* row = buf + (nt * 8 + r) * ROWB + q * 8;
            float a00 = 0, a01 = 0, a02 = 0, a03 = 0;   // tile0 chain A
            float b00 = 0, b01 = 0, b02 = 0, b03 = 0;   // tile0 chain B
            float a10 = 0, a11 = 0, a12 = 0, a13 = 0;   // tile1 chain A
            float b10 = 0, b11 = 0, b12 = 0, b13 = 0;   // tile1 chain B
            #pragma unroll
            for (int ks = 0; ks < 2; ks++) {
                unsigned long long bwA =
                    *(const unsigned long long*)(row + ks * 32);
                unsigned long long bwB =
                    *(const unsigned long long*)(row + (ks + 2) * 32);
                unsigned bA0 = (unsigned)bwA, bA1 = (unsigned)(bwA >> 32);
                unsigned bB0 = (unsigned)bwB, bB1 = (unsigned)(bwB >> 32);
                MMA_F16(a00, a01, a02, a03,
                        ahi[0][ks][0], ahi[1][ks][0],
                        ahi[0][ks][1], ahi[1][ks][1], bA0, bA1);
                MMA_F16(b00, b01, b02, b03,
                        ahi[0][ks + 2][0], ahi[1][ks + 2][0],
                        ahi[0][ks + 2][1], ahi[1][ks + 2][1], bB0, bB1);
                MMA_F16(a10, a11, a12, a13,
                        ahi[2][ks][0], ahi[3][ks][0],
                        ahi[2][ks][1], ahi[3][ks][1], bA0, bA1);
                MMA_F16(b10, b11, b12, b13,
                        ahi[2][ks + 2][0], ahi[3][ks + 2][0],
                        ahi[2][ks + 2][1], ahi[3][ks + 2][1], bB0, bB1);
            }
            int c0 = cbase + nt * 8 + 2 * q;
            float en0 = sEN[c0], en1 = sEN[c0 + 1];
            float k00 = __fmaf_rn(-2.0f, __fadd_rn(a00, b00), en0);
            float k01 = __fmaf_rn(-2.0f, __fadd_rn(a01, b01), en1);
            float k02 = __fmaf_rn(-2.0f, __fadd_rn(a02, b02), en0);
            float k03 = __fmaf_rn(-2.0f, __fadd_rn(a03, b03), en1);
            float k10 = __fmaf_rn(-2.0f, __fadd_rn(a10, b10), en0);
            float k11 = __fmaf_rn(-2.0f, __fadd_rn(a11, b11), en1);
            float k12 = __fmaf_rn(-2.0f, __fadd_rn(a12, b12), en0);
            float k13 = __fmaf_rn(-2.0f, __fadd_rn(a13, b13), en1);

            cm[0] = fminf(cm[0], fminf(k00, k01));
            cm[1] = fminf(cm[1], fminf(k02, k03));
            cm[2] = fminf(cm[2], fminf(k10, k11));
            cm[3] = fminf(cm[3], fminf(k12, k13));

            if (k00 < b1v[0]) { b2v[0]=b1v[0]; b1v[0]=k00; i1v[0]=c0; }
            else if (k00 < b2v[0]) b2v[0]=k00;
            if (k01 < b1v[0]) { b2v[0]=b1v[0]; b1v[0]=k01; i1v[0]=c0+1; }
            else if (k01 < b2v[0]) b2v[0]=k01;
            if (k02 < b1v[1]) { b2v[1]=b1v[1]; b1v[1]=k02; i1v[1]=c0; }
            else if (k02 < b2v[1]) b2v[1]=k02;
            if (k03 < b1v[1]) { b2v[1]=b1v[1]; b1v[1]=k03; i1v[1]=c0+1; }
            else if (k03 < b2v[1]) b2v[1]=k03;
            if (k10 < b1v[2]) { b2v[2]=b1v[2]; b1v[2]=k10; i1v[2]=c0; }
            else if (k10 < b2v[2]) b2v[2]=k10;
            if (k11 < b1v[2]) { b2v[2]=b1v[2]; b1v[2]=k11; i1v[2]=c0+1; }
            else if (k11 < b2v[2]) b2v[2]=k11;
            if (k12 < b1v[3]) { b2v[3]=b1v[3]; b1v[3]=k12; i1v[3]=c0; }
            else if (k12 < b2v[3]) b2v[3]=k12;
            if (k13 < b1v[3]) { b2v[3]=b1v[3]; b1v[3]=k13; i1v[3]=c0+1; }
            else if (k13 < b2v[3]) b2v[3]=k13;
        }

        #pragma unroll
        for (int s = 0; s < 4; s++) {
            cm[s] = fminf(cm[s], __shfl_xor_sync(0xffffffffu, cm[s], 1));
            cm[s] = fminf(cm[s], __shfl_xor_sync(0xffffffffu, cm[s], 2));
        }
        if (q == 0) {
            #pragma unroll
            for (int s = 0; s < 4; s++)
                scmin[wid * 32 + s * 8 + r][c] = cm[s];
        }
        __syncthreads();
    }

    // ---- merge best1/best2 across the 4 q-lanes of each row group ----
    #pragma unroll
    for (int s = 0; s < 4; s++) {
        #pragma unroll
        for (int m = 1; m <= 2; m <<= 1) {
            float ob1 = __shfl_xor_sync(0xffffffffu, b1v[s], m);
            int   oi1 = __shfl_xor_sync(0xffffffffu, i1v[s], m);
            float ob2 = __shfl_xor_sync(0xffffffffu, b2v[s], m);
            bool take = (ob1 < b1v[s]) || (ob1 == b1v[s] && oi1 < i1v[s]);
            float nb2 = take ? fminf(b1v[s], ob2) : fminf(b2v[s], ob1);
            if (take) { b1v[s] = ob1; i1v[s] = oi1; }
            b2v[s] = nb2;
        }
    }

    if (q == 0) {
        #pragma unroll
        for (int s = 0; s < 4; s++) {
            int lt    = wid * 32 + s * 8 + r;
            int token = blockIdx.x * 256 + lt;
            g_idx[token] = i1v[s];
            float th = __fadd_rn(b1v[s], mg[s]);
            if (b2v[s] <= th) {
                unsigned mask = 0;
                #pragma unroll
                for (int c = 0; c < 16; c++)
                    if (scmin[lt][c] <= th) mask |= (1u << c);
                int p = atomicAdd(&s_nf, 1);
                s_fl[p] = ((unsigned)lt << 16) | mask;
            }
        }
    }
    __syncthreads();

    // ---- fused refine tail: warp per flagged token, masked chunks only ----
    int nf = s_nf;
    for (int f = wid; f < nf; f += 8) {
        unsigned e = s_fl[f];
        int lt = (int)(e >> 16);
        unsigned mask = e & 0xFFFFu;
        int token = blockIdx.x * 256 + lt;

        // stage x row into this warp's smem slot (then broadcast reads)
        float2 xv = __ldg(((const float2*)(x + ((size_t)token << 6))) + lane);
        sxs[wid][2 * lane]     = xv.x;
        sxs[wid][2 * lane + 1] = xv.y;
        __syncwarp();

        // xn: identical sequential rounding tree (all lanes redundantly)
        float xn = 0.0f;
        #pragma unroll
        for (int d = 0; d < DIM; d++)
            xn = __fmaf_rn(sxs[wid][d], sxs[wid][d], xn);

        unsigned long long bkey = 0xFFFFFFFFFFFFFFFFull;
        while (mask) {
            int c = __ffs(mask) - 1;
            mask &= mask - 1;
            #pragma unroll
            for (int half = 0; half < 2; half++) {
                int code = c * 64 + half * 32 + lane;
                const float4* er = (const float4*)(emb + (size_t)code * DIM);
                float s[8] = {0, 0, 0, 0, 0, 0, 0, 0};
                #pragma unroll
                for (int jj = 0; jj < 8; jj++) {
                    float4 e0 = __ldg(er + 2 * jj);
                    float4 e1 = __ldg(er + 2 * jj + 1);
                    s[0] = __fmaf_rn(sxs[wid][jj * 8 + 0], e0.x, s[0]);
                    s[1] = __fmaf_rn(sxs[wid][jj * 8 + 1], e0.y, s[1]);
                    s[2] = __fmaf_rn(sxs[wid][jj * 8 + 2], e0.z, s[2]);
                    s[3] = __fmaf_rn(sxs[wid][jj * 8 + 3], e0.w, s[3]);
                    s[4] = __fmaf_rn(sxs[wid][jj * 8 + 4], e1.x, s[4]);
                    s[5] = __fmaf_rn(sxs[wid][jj * 8 + 5], e1.y, s[5]);
                    s[6] = __fmaf_rn(sxs[wid][jj * 8 + 6], e1.z, s[6]);
                    s[7] = __fmaf_rn(sxs[wid][jj * 8 + 7], e1.w, s[7]);
                }
                float lo  = __fadd_rn(__fadd_rn(s[0], s[2]), __fadd_rn(s[4], s[6]));
                float hi  = __fadd_rn(__fadd_rn(s[1], s[3]), __fadd_rn(s[5], s[7]));
                float dot = __fadd_rn(lo, hi);
                float d2  = __fadd_rn(__fmaf_rn(-2.0f, dot, xn), sEN[code]);
                unsigned long long key =
                    ((unsigned long long)fkey(d2) << 32) | (unsigned)code;
                if (key < bkey) bkey = key;
            }
        }
        #pragma unroll
        for (int off = 16; off > 0; off >>= 1) {
            unsigned long long o = __shfl_xor_sync(0xffffffffu, bkey, off);
            if (o < bkey) bkey = o;
        }
        if (lane == 0) g_idx[token] = (int)(bkey & 0xFFFFFFFFull);
    }
}

// ---------------------------------------------------------------------------
// Kernel 2: epilogue — 8 threads/token; v4 REDG; 1 loss atomic/CTA (R13-best)
// ---------------------------------------------------------------------------
__global__ __launch_bounds__(256)
void epilogue_kernel(const float* __restrict__ x,
                     const float* __restrict__ emb,
                     float* __restrict__ out) {
    __shared__ double sred[8];
    int gid   = blockIdx.x * 256 + threadIdx.x;
    int token = gid >> 3;
    int part  = gid & 7;
    int bi = g_idx[token];

    const float4* xrow = (const float4*)(x + ((size_t)token << 6)) + part * 2;
    const float4* erow = (const float4*)(emb + ((size_t)bi << 6)) + part * 2;
    float4* orow = (float4*)(out + OFF_Q + ((size_t)token << 6)) + part * 2;
    float* dwrow = g_dw + ((size_t)bi << 6) + part * 8;

    float lsum = 0.0f;
    #pragma unroll
    for (int j = 0; j < 2; j++) {
        float4 xv = __ldg(xrow + j);
        float4 q  = __ldg(erow + j);
        float4 o;
        o.x = __fadd_rn(xv.x, __fadd_rn(q.x, -xv.x));
        o.y = __fadd_rn(xv.y, __fadd_rn(q.y, -xv.y));
        o.z = __fadd_rn(xv.z, __fadd_rn(q.z, -xv.z));
        o.w = __fadd_rn(xv.w, __fadd_rn(q.w, -xv.w));
        orow[j] = o;
        float d0 = __fadd_rn(xv.x, -q.x);
        float d1 = __fadd_rn(xv.y, -q.y);
        float d2 = __fadd_rn(xv.z, -q.z);
        float d3 = __fadd_rn(xv.w, -q.w);
        lsum = __fmaf_rn(d0, d0, lsum);
        lsum = __fmaf_rn(d1, d1, lsum);
        lsum = __fmaf_rn(d2, d2, lsum);
        lsum = __fmaf_rn(d3, d3, lsum);
        asm volatile("red.global.add.v4.f32 [%0], {%1, %2, %3, %4};"
                     :: "l"(dwrow + 4 * j),
                        "f"(xv.x), "f"(xv.y), "f"(xv.z), "f"(xv.w)
                     : "memory");
    }
    if (part == 0) atomicAdd(&g_counts[bi], 1.0f);

    double dl = (double)lsum;
    #pragma unroll
    for (int off = 16; off > 0; off >>= 1)
        dl += __shfl_down_sync(0xffffffffu, dl, off);
    if ((threadIdx.x & 31) == 0) sred[threadIdx.x >> 5] = dl;
    __syncthreads();
    if (threadIdx.x == 0) {
        double t = ((sred[0] + sred[1]) + (sred[2] + sred[3]))
                 + ((sred[4] + sred[5]) + (sred[6] + sred[7]));
        atomicAdd(&g_loss, t);
    }
}

// ---------------------------------------------------------------------------
// Kernel 3: merged finalize + ema (R14-validated). Grid 64 x 1024 threads.
// ---------------------------------------------------------------------------
__global__ void finalize_ema_kernel(const float* __restrict__ ema_count,
                                    const float* __restrict__ ema_weight,
                                    const float* __restrict__ usage,
                                    float* __restrict__ out) {
    __shared__ float red_n[1024];
    __shared__ float red_s[1024];
    int t = threadIdx.x;

    float c   = g_counts[t];
    float raw = __fadd_rn(__fmul_rn(0.999f, ema_count[t]), __fmul_rn(0.001f, c));

    float p   = c * (1.0f / 65536.0f);
    float ent = __fmul_rn(p, logf(__fadd_rn(p, 1e-10f)));

    red_n[t] = raw;
    red_s[t] = ent;
    __syncthreads();
    for (int s = 512; s > 0; s >>= 1) {
        if (t < s) {
            red_n[t] = __fadd_rn(red_n[t], red_n[t + s]);
            red_s[t] = __fadd_rn(red_s[t], red_s[t + s]);
        }
        __syncthreads();
    }
    float n    = red_n[0];
    float ssum = red_s[0];

    // ---- ema slice (codes blockIdx.x*16 .. +15) ----
    int idx  = blockIdx.x * 1024 + t;
    int code = idx >> 6;
    float craw = __fadd_rn(__fmul_rn(0.999f, __ldg(ema_count + code)),
                           __fmul_rn(0.001f, g_counts[code]));
    float cncnt = __fmul_rn(__fdiv_rn(__fadd_rn(craw, 1e-5f),
                                      __fadd_rn(n, 0.01024f)), n);
    float nw = __fadd_rn(__fmul_rn(0.999f, __ldg(ema_weight + idx)),
                         __fmul_rn(0.001f, g_dw[idx]));
    out[OFF_W + idx] = nw;
    out[OFF_E + idx] = __fdiv_rn(nw, cncnt);

    // ---- CTA 0: counts / usage / scalars ----
    if (blockIdx.x == 0) {
        float ncnt = __fmul_rn(__fdiv_rn(__fadd_rn(raw, 1e-5f),
                                         __fadd_rn(n, 0.01024f)), n);
        out[OFF_CNT + t] = ncnt;
        out[OFF_USE + t] = __fmul_rn(__fadd_rn(__ldg(usage + t),
                                               (c > 0.0f) ? 1.0f : 0.0f), 0.5f);
        if (t == 0) {
            float ml = (float)(g_loss * (1.0 / 4194304.0));
            out[OFF_CB] = ml;
            out[OFF_CM] = 0.25f * ml;
            out[OFF_P]  = expf(-ssum);
        }
    }
}

// ---------------------------------------------------------------------------
extern "C" void kernel_launch(void* const* d_in, const int* in_sizes, int n_in,
                              void* d_out, int out_size) {
    const float* x          = (const float*)d_in[0];
    const float* emb        = (const float*)d_in[1];
    const float* ema_count  = (const float*)d_in[2];
    const float* ema_weight = (const float*)d_in[3];
    const float* usage      = (const float*)d_in[4];
    float* out = (float*)d_out;

    setup_kernel<<<256, 256>>>(emb);
    mma_assign_kernel<<<NTOK / 256, 256>>>(x, emb);
    epilogue_kernel<<<NTOK * 8 / 256, 256>>>(x, emb, out);
    finalize_ema_kernel<<<64, 1024>>>(ema_count, ema_weight, usage, out);
}

// round 17
// speedup vs baseline: 1.0650x; 1.0316x over previous
#include <cuda_runtime.h>
#include <cuda_fp16.h>
#include <math.h>
#include <float.h>

// Problem constants
#define NTOK   65536
#define DIM    64
#define KCODES 1024

// Certified margin (validated in R7/R12): mg = MGK * sum|x| + MGS
#define MGK   1.47e-4f
#define MGS   3e-4f

// Output layout (float32 concatenation of the reference tuple)
#define OFF_Q    0
#define OFF_CM   4194304
#define OFF_CB   4194305
#define OFF_P    4194306
#define OFF_E    4194307
#define OFF_CNT  (OFF_E + KCODES*DIM)
#define OFF_W    (OFF_CNT + KCODES)
#define OFF_USE  (OFF_W + KCODES*DIM)

// Scratch (static device globals; no cudaMalloc allowed)
__device__ float          g_counts[KCODES];
__device__ float          g_dw[KCODES * DIM];
__device__ float          g_enorm[KCODES];
__device__ unsigned short g_staged[KCODES * 64];   // fp16 fragment-permuted B
__device__ double         g_loss;

#define MMA_F16(d0,d1,d2,d3,a0,a1,a2,a3,b0,b1)                                \
    asm("mma.sync.aligned.m16n8k16.row.col.f32.f16.f16.f32 "                  \
        "{%0,%1,%2,%3}, {%4,%5,%6,%7}, {%8,%9}, {%0,%1,%2,%3};"               \
        : "+f"(d0), "+f"(d1), "+f"(d2), "+f"(d3)                              \
        : "r"(a0), "r"(a1), "r"(a2), "r"(a3), "r"(b0), "r"(b1))

__device__ __forceinline__ unsigned pack_h2(float lo, float hi) {
    __half2 h = __floats2half2_rn(lo, hi);
    return *(unsigned*)&h;
}
__device__ __forceinline__ unsigned fkey(float f) {
    unsigned u = __float_as_uint(f);
    return (u & 0x80000000u) ? ~u : (u | 0x80000000u);
}

// ---------------------------------------------------------------------------
// Kernel 0: zero scratch; enorm; fp16 fragment-permuted B (R7-validated).
// ---------------------------------------------------------------------------
__global__ void setup_kernel(const float* __restrict__ emb) {
    int gtid = blockIdx.x * 256 + threadIdx.x;      // 0..65535
    g_dw[gtid] = 0.0f;
    if (gtid < KCODES) g_counts[gtid] = 0.0f;
    if (gtid == 0) g_loss = 0.0;

    int c = gtid >> 6;      // code
    int d = gtid & 63;      // dim
    float e = __ldg(emb + gtid);
    __half hb = __float2half_rn(e);

    int p   = d >> 1;
    int ks  = p >> 3;
    int pos = p & 7;
    int w   = (pos < 4) ? 2 * (ks * 4 + pos) : 2 * (ks * 4 + pos - 4) + 1;
    g_staged[c * 64 + w * 2 + (d & 1)] = __half_as_ushort(hb);

    // enorm (identical reduction tree to the passing kernels)
    if (blockIdx.x < 64) {
        int code = blockIdx.x * 16 + (threadIdx.x >> 4);
        int sub  = threadIdx.x & 15;
        float4 v = __ldg(((const float4*)(emb + (size_t)code * DIM)) + sub);
        float s = __fmul_rn(v.x, v.x);
        s = __fmaf_rn(v.y, v.y, s);
        s = __fmaf_rn(v.z, v.z, s);
        s = __fmaf_rn(v.w, v.w, s);
        #pragma unroll
        for (int off = 8; off > 0; off >>= 1)
            s = __fadd_rn(s, __shfl_down_sync(0xffffffffu, s, off));
        if (sub == 0) g_enorm[code] = s;
    }
}

// ---------------------------------------------------------------------------
// Kernel 1: fp16 1-split MMA assign + per-chunk min (R12/R13-proven hot loop)
// + FUSED refine tail (R16-validated) + FUSED epilogue tail (new):
// each CTA finishes its own 256 tokens end-to-end; indices stay in smem.
// ---------------------------------------------------------------------------
#define ROWB 160              // B smem row stride bytes (128 + 32)

__global__ __launch_bounds__(256, 2)
void mma_assign_kernel(const float* __restrict__ x,
                       const float* __restrict__ emb,
                       float* __restrict__ out) {
    __shared__ __align__(16) unsigned char sbuf[2][64 * ROWB];  // 20 KB
    __shared__ float sEN[KCODES];                                // 4 KB
    __shared__ float scmin[256][16];                             // 16 KB
    __shared__ unsigned s_fl[256];                               // 1 KB
    __shared__ int s_idx[256];                                   // 1 KB
    __shared__ int s_nf;
    __shared__ float sxs[8][64];                                 // 2 KB
    __shared__ double sred[8];

    int tid  = threadIdx.x;
    int lane = tid & 31;
    int wid  = tid >> 5;
    int r    = lane >> 2;
    int q    = lane & 3;
    int warptok = blockIdx.x * 256 + wid * 32;

    if (tid == 0) s_nf = 0;

    unsigned sb[2];
    asm("{ .reg .u64 t; cvta.to.shared.u64 t, %1; cvt.u32.u64 %0, t; }"
        : "=r"(sb[0]) : "l"(sbuf[0]));
    asm("{ .reg .u64 t; cvta.to.shared.u64 t, %1; cvt.u32.u64 %0, t; }"
        : "=r"(sb[1]) : "l"(sbuf[1]));

    // prefetch chunk 0 (64 codes x 128 B = 512 16B pieces)
    {
        const float4* src = (const float4*)g_staged;
        #pragma unroll
        for (int k2 = 0; k2 < 2; k2++) {
            int p = tid + k2 * 256;
            asm volatile("cp.async.cg.shared.global [%0], [%1], 16;"
                :: "r"(sb[0] + (p >> 3) * ROWB + (p & 7) * 16), "l"(src + p)
                : "memory");
        }
        asm volatile("cp.async.commit_group;" ::: "memory");
    }

    // en table
    #pragma unroll
    for (int i = 0; i < 4; i++) sEN[i * 256 + tid] = g_enorm[i * 256 + tid];

    // ---- A fragments (fp16) + per-row-group |x| sums ----
    unsigned ahi[4][4][2];
    float sabs[4] = {0, 0, 0, 0};
    #pragma unroll
    for (int g = 0; g < 4; g++) {
        const float* xr = x + (size_t)(warptok + g * 8 + r) * DIM + 2 * q;
        #pragma unroll
        for (int ks = 0; ks < 4; ks++) {
            float2 v0 = __ldg((const float2*)(xr + 16 * ks));
            float2 v1 = __ldg((const float2*)(xr + 16 * ks + 8));
            ahi[g][ks][0] = pack_h2(v0.x, v0.y);
            ahi[g][ks][1] = pack_h2(v1.x, v1.y);
            sabs[g] += ((fabsf(v0.x) + fabsf(v0.y)) +
                        (fabsf(v1.x) + fabsf(v1.y)));
        }
    }
    float mg[4];
    #pragma unroll
    for (int g = 0; g < 4; g++) {
        float s = sabs[g];
        s += __shfl_xor_sync(0xffffffffu, s, 1);
        s += __shfl_xor_sync(0xffffffffu, s, 2);
        mg[g] = __fmaf_rn(s, MGK, MGS);
    }
    __syncthreads();

    float b1v[4] = {FLT_MAX, FLT_MAX, FLT_MAX, FLT_MAX};
    float b2v[4] = {FLT_MAX, FLT_MAX, FLT_MAX, FLT_MAX};
    int   i1v[4] = {0, 0, 0, 0};

    for (int c = 0; c < 16; c++) {
        if (c + 1 < 16) {
            const float4* src = ((const float4*)g_staged) + (c + 1) * 512;
            unsigned dst = sb[(c + 1) & 1];
            #pragma unroll
            for (int k2 = 0; k2 < 2; k2++) {
                int p = tid + k2 * 256;
                asm volatile("cp.async.cg.shared.global [%0], [%1], 16;"
                    :: "r"(dst + (p >> 3) * ROWB + (p & 7) * 16), "l"(src + p)
                    : "memory");
            }
            asm volatile("cp.async.commit_group;" ::: "memory");
            asm volatile("cp.async.wait_group 1;" ::: "memory");
        } else {
            asm volatile("cp.async.wait_group 0;" ::: "memory");
        }
        __syncthreads();

        const unsigned char* buf = sbuf[c & 1];
        int cbase = c * 64;
        float cm[4] = {FLT_MAX, FLT_MAX, FLT_MAX, FLT_MAX};

        #pragma unroll 2
        for (int nt = 0; nt < 8; nt++) {
            const unsigned char* row = buf + (nt * 8 + r) * ROWB + q * 8;
            float a00 = 0, a01 = 0, a02 = 0, a03 = 0;   // tile0 chain A
            float b00 = 0, b01 = 0, b02 = 0, b03 = 0;   // tile0 chain B
            float a10 = 0, a11 = 0, a12 = 0, a13 = 0;   // tile1 chain A
            float b10 = 0, b11 = 0, b12 = 0, b13 = 0;   // tile1 chain B
            #pragma unroll
            for (int ks = 0; ks < 2; ks++) {
                unsigned long long bwA =
                    *(const unsigned long long*)(row + ks * 32);
                unsigned long long bwB =
                    *(const unsigned long long*)(row + (ks + 2) * 32);
                unsigned bA0 = (unsigned)bwA, bA1 = (unsigned)(bwA >> 32);
                unsigned bB0 = (unsigned)bwB, bB1 = (unsigned)(bwB >> 32);
                MMA_F16(a00, a01, a02, a03,
                        ahi[0][ks][0], ahi[1][ks][0],
                        ahi[0][ks][1], ahi[1][ks][1], bA0, bA1);
                MMA_F16(b00, b01, b02, b03,
                        ahi[0][ks + 2][0], ahi[1][ks + 2][0],
                        ahi[0][ks + 2][1], ahi[1][ks + 2][1], bB0, bB1);
                MMA_F16(a10, a11, a12, a13,
                        ahi[2][ks][0], ahi[3][ks][0],
                        ahi[2][ks][1], ahi[3][ks][1], bA0, bA1);
                MMA_F16(b10, b11, b12, b13,
                        ahi[2][ks + 2][0], ahi[3][ks + 2][0],
                        ahi[2][ks + 2][1], ahi[3][ks + 2][1], bB0, bB1);
            }
            int c0 = cbase + nt * 8 + 2 * q;
            float en0 = sEN[c0], en1 = sEN[c0 + 1];
            float k00 = __fmaf_rn(-2.0f, __fadd_rn(a00, b00), en0);
            float k01 = __fmaf_rn(-2.0f, __fadd_rn(a01, b01), en1);
            float k02 = __fmaf_rn(-2.0f, __fadd_rn(a02, b02), en0);
            float k03 = __fmaf_rn(-2.0f, __fadd_rn(a03, b03), en1);
            float k10 = __fmaf_rn(-2.0f, __fadd_rn(a10, b10), en0);
            float k11 = __fmaf_rn(-2.0f, __fadd_rn(a11, b11), en1);
            float k12 = __fmaf_rn(-2.0f, __fadd_rn(a12, b12), en0);
            float k13 = __fmaf_rn(-2.0f, __fadd_rn(a13, b13), en1);

            cm[0] = fminf(cm[0], fminf(k00, k01));
            cm[1] = fminf(cm[1], fminf(k02, k03));
            cm[2] = fminf(cm[2], fminf(k10, k11));
            cm[3] = fminf(cm[3], fminf(k12, k13));

            if (k00 < b1v[0]) { b2v[0]=b1v[0]; b1v[0]=k00; i1v[0]=c0; }
            else if (k00 < b2v[0]) b2v[0]=k00;
            if (k01 < b1v[0]) { b2v[0]=b1v[0]; b1v[0]=k01; i1v[0]=c0+1; }
            else if (k01 < b2v[0]) b2v[0]=k01;
            if (k02 < b1v[1]) { b2v[1]=b1v[1]; b1v[1]=k02; i1v[1]=c0; }
            else if (k02 < b2v[1]) b2v[1]=k02;
            if (k03 < b1v[1]) { b2v[1]=b1v[1]; b1v[1]=k03; i1v[1]=c0+1; }
            else if (k03 < b2v[1]) b2v[1]=k03;
            if (k10 < b1v[2]) { b2v[2]=b1v[2]; b1v[2]=k10; i1v[2]=c0; }
            else if (k10 < b2v[2]) b2v[2]=k10;
            if (k11 < b1v[2]) { b2v[2]=b1v[2]; b1v[2]=k11; i1v[2]=c0+1; }
            else if (k11 < b2v[2]) b2v[2]=k11;
            if (k12 < b1v[3]) { b2v[3]=b1v[3]; b1v[3]=k12; i1v[3]=c0; }
            else if (k12 < b2v[3]) b2v[3]=k12;
            if (k13 < b1v[3]) { b2v[3]=b1v[3]; b1v[3]=k13; i1v[3]=c0+1; }
            else if (k13 < b2v[3]) b2v[3]=k13;
        }

        #pragma unroll
        for (int s = 0; s < 4; s++) {
            cm[s] = fminf(cm[s], __shfl_xor_sync(0xffffffffu, cm[s], 1));
            cm[s] = fminf(cm[s], __shfl_xor_sync(0xffffffffu, cm[s], 2));
        }
        if (q == 0) {
            #pragma unroll
            for (int s = 0; s < 4; s++)
                scmin[wid * 32 + s * 8 + r][c] = cm[s];
        }
        __syncthreads();
    }

    // ---- merge best1/best2 across the 4 q-lanes of each row group ----
    #pragma unroll
    for (int s = 0; s < 4; s++) {
        #pragma unroll
        for (int m = 1; m <= 2; m <<= 1) {
            float ob1 = __shfl_xor_sync(0xffffffffu, b1v[s], m);
            int   oi1 = __shfl_xor_sync(0xffffffffu, i1v[s], m);
            float ob2 = __shfl_xor_sync(0xffffffffu, b2v[s], m);
            bool take = (ob1 < b1v[s]) || (ob1 == b1v[s] && oi1 < i1v[s]);
            float nb2 = take ? fminf(b1v[s], ob2) : fminf(b2v[s], ob1);
            if (take) { b1v[s] = ob1; i1v[s] = oi1; }
            b2v[s] = nb2;
        }
    }

    if (q == 0) {
        #pragma unroll
        for (int s = 0; s < 4; s++) {
            int lt = wid * 32 + s * 8 + r;
            s_idx[lt] = i1v[s];
            float th = __fadd_rn(b1v[s], mg[s]);
            if (b2v[s] <= th) {
                unsigned mask = 0;
                #pragma unroll
                for (int c = 0; c < 16; c++)
                    if (scmin[lt][c] <= th) mask |= (1u << c);
                int p = atomicAdd(&s_nf, 1);
                s_fl[p] = ((unsigned)lt << 16) | mask;
            }
        }
    }
    __syncthreads();

    // ---- fused refine tail: warp per flagged token, masked chunks only ----
    int nf = s_nf;
    for (int f = wid; f < nf; f += 8) {
        unsigned e = s_fl[f];
        int lt = (int)(e >> 16);
        unsigned mask = e & 0xFFFFu;
        int token = blockIdx.x * 256 + lt;

        float2 xv = __ldg(((const float2*)(x + ((size_t)token << 6))) + lane);
        sxs[wid][2 * lane]     = xv.x;
        sxs[wid][2 * lane + 1] = xv.y;
        __syncwarp();

        float xn = 0.0f;
        #pragma unroll
        for (int d = 0; d < DIM; d++)
            xn = __fmaf_rn(sxs[wid][d], sxs[wid][d], xn);

        unsigned long long bkey = 0xFFFFFFFFFFFFFFFFull;
        while (mask) {
            int c = __ffs(mask) - 1;
            mask &= mask - 1;
            #pragma unroll
            for (int half = 0; half < 2; half++) {
                int code = c * 64 + half * 32 + lane;
                const float4* er = (const float4*)(emb + (size_t)code * DIM);
                float s[8] = {0, 0, 0, 0, 0, 0, 0, 0};
                #pragma unroll
                for (int jj = 0; jj < 8; jj++) {
                    float4 e0 = __ldg(er + 2 * jj);
                    float4 e1 = __ldg(er + 2 * jj + 1);
                    s[0] = __fmaf_rn(sxs[wid][jj * 8 + 0], e0.x, s[0]);
                    s[1] = __fmaf_rn(sxs[wid][jj * 8 + 1], e0.y, s[1]);
                    s[2] = __fmaf_rn(sxs[wid][jj * 8 + 2], e0.z, s[2]);
                    s[3] = __fmaf_rn(sxs[wid][jj * 8 + 3], e0.w, s[3]);
                    s[4] = __fmaf_rn(sxs[wid][jj * 8 + 4], e1.x, s[4]);
                    s[5] = __fmaf_rn(sxs[wid][jj * 8 + 5], e1.y, s[5]);
                    s[6] = __fmaf_rn(sxs[wid][jj * 8 + 6], e1.z, s[6]);
                    s[7] = __fmaf_rn(sxs[wid][jj * 8 + 7], e1.w, s[7]);
                }
                float lo  = __fadd_rn(__fadd_rn(s[0], s[2]), __fadd_rn(s[4], s[6]));
                float hi  = __fadd_rn(__fadd_rn(s[1], s[3]), __fadd_rn(s[5], s[7]));
                float dot = __fadd_rn(lo, hi);
                float d2  = __fadd_rn(__fmaf_rn(-2.0f, dot, xn), sEN[code]);
                unsigned long long key =
                    ((unsigned long long)fkey(d2) << 32) | (unsigned)code;
                if (key < bkey) bkey = key;
            }
        }
        #pragma unroll
        for (int off = 16; off > 0; off >>= 1) {
            unsigned long long o = __shfl_xor_sync(0xffffffffu, bkey, off);
            if (o < bkey) bkey = o;
        }
        if (lane == 0) s_idx[lt] = (int)(bkey & 0xFFFFFFFFull);
    }
    __syncthreads();

    // ---- fused epilogue: 2048 (token,part) items over 256 threads ----
    double dl = 0.0;
    #pragma unroll 1
    for (int it = 0; it < 8; it++) {
        int gid   = it * 256 + tid;
        int lt    = gid >> 3;
        int part  = gid & 7;
        int token = blockIdx.x * 256 + lt;
        int bi    = s_idx[lt];

        const float4* xrow = (const float4*)(x + ((size_t)token << 6)) + part * 2;
        const float4* erow = (const float4*)(emb + ((size_t)bi << 6)) + part * 2;
        float4* orow = (float4*)(out + OFF_Q + ((size_t)token << 6)) + part * 2;
        float* dwrow = g_dw + ((size_t)bi << 6) + part * 8;

        float lsum = 0.0f;
        #pragma unroll
        for (int j = 0; j < 2; j++) {
            float4 xv = __ldg(xrow + j);
            float4 qv = __ldg(erow + j);
            float4 o;
            o.x = __fadd_rn(xv.x, __fadd_rn(qv.x, -xv.x));
            o.y = __fadd_rn(xv.y, __fadd_rn(qv.y, -xv.y));
            o.z = __fadd_rn(xv.z, __fadd_rn(qv.z, -xv.z));
            o.w = __fadd_rn(xv.w, __fadd_rn(qv.w, -xv.w));
            orow[j] = o;
            float d0 = __fadd_rn(xv.x, -qv.x);
            float d1 = __fadd_rn(xv.y, -qv.y);
            float d2 = __fadd_rn(xv.z, -qv.z);
            float d3 = __fadd_rn(xv.w, -qv.w);
            lsum = __fmaf_rn(d0, d0, lsum);
            lsum = __fmaf_rn(d1, d1, lsum);
            lsum = __fmaf_rn(d2, d2, lsum);
            lsum = __fmaf_rn(d3, d3, lsum);
            asm volatile("red.global.add.v4.f32 [%0], {%1, %2, %3, %4};"
                         :: "l"(dwrow + 4 * j),
                            "f"(xv.x), "f"(xv.y), "f"(xv.z), "f"(xv.w)
                         : "memory");
        }
        if (part == 0) atomicAdd(&g_counts[bi], 1.0f);
        dl += (double)lsum;
    }

    #pragma unroll
    for (int off = 16; off > 0; off >>= 1)
        dl += __shfl_down_sync(0xffffffffu, dl, off);
    if (lane == 0) sred[wid] = dl;
    __syncthreads();
    if (tid == 0) {
        double t = ((sred[0] + sred[1]) + (sred[2] + sred[3]))
                 + ((sred[4] + sred[5]) + (sred[6] + sred[7]));
        atomicAdd(&g_loss, t);
    }
}

// ---------------------------------------------------------------------------
// Kernel 2: merged finalize + ema (R14-validated). Grid 64 x 1024 threads.
// ---------------------------------------------------------------------------
__global__ void finalize_ema_kernel(const float* __restrict__ ema_count,
                                    const float* __restrict__ ema_weight,
                                    const float* __restrict__ usage,
                                    float* __restrict__ out) {
    __shared__ float red_n[1024];
    __shared__ float red_s[1024];
    int t = threadIdx.x;

    float c   = g_counts[t];
    float raw = __fadd_rn(__fmul_rn(0.999f, ema_count[t]), __fmul_rn(0.001f, c));

    float p   = c * (1.0f / 65536.0f);
    float ent = __fmul_rn(p, logf(__fadd_rn(p, 1e-10f)));

    red_n[t] = raw;
    red_s[t] = ent;
    __syncthreads();
    for (int s = 512; s > 0; s >>= 1) {
        if (t < s) {
            red_n[t] = __fadd_rn(red_n[t], red_n[t + s]);
            red_s[t] = __fadd_rn(red_s[t], red_s[t + s]);
        }
        __syncthreads();
    }
    float n    = red_n[0];
    float ssum = red_s[0];

    // ---- ema slice (codes blockIdx.x*16 .. +15) ----
    int idx  = blockIdx.x * 1024 + t;
    int code = idx >> 6;
    float craw = __fadd_rn(__fmul_rn(0.999f, __ldg(ema_count + code)),
                           __fmul_rn(0.001f, g_counts[code]));
    float cncnt = __fmul_rn(__fdiv_rn(__fadd_rn(craw, 1e-5f),
                                      __fadd_rn(n, 0.01024f)), n);
    float nw = __fadd_rn(__fmul_rn(0.999f, __ldg(ema_weight + idx)),
                         __fmul_rn(0.001f, g_dw[idx]));
    out[OFF_W + idx] = nw;
    out[OFF_E + idx] = __fdiv_rn(nw, cncnt);

    // ---- CTA 0: counts / usage / scalars ----
    if (blockIdx.x == 0) {
        float ncnt = __fmul_rn(__fdiv_rn(__fadd_rn(raw, 1e-5f),
                                         __fadd_rn(n, 0.01024f)), n);
        out[OFF_CNT + t] = ncnt;
        out[OFF_USE + t] = __fmul_rn(__fadd_rn(__ldg(usage + t),
                                               (c > 0.0f) ? 1.0f : 0.0f), 0.5f);
        if (t == 0) {
            float ml = (float)(g_loss * (1.0 / 4194304.0));
            out[OFF_CB] = ml;
            out[OFF_CM] = 0.25f * ml;
            out[OFF_P]  = expf(-ssum);
        }
    }
}

// ---------------------------------------------------------------------------
extern "C" void kernel_launch(void* const* d_in, const int* in_sizes, int n_in,
                              void* d_out, int out_size) {
    const float* x          = (const float*)d_in[0];
    const float* emb        = (const float*)d_in[1];
    const float* ema_count  = (const float*)d_in[2];
    const float* ema_weight = (const float*)d_in[3];
    const float* usage      = (const float*)d_in[4];
    float* out = (float*)d_out;

    setup_kernel<<<256, 256>>>(emb);
    mma_assign_kernel<<<NTOK / 256, 256>>>(x, emb, out);
    finalize_ema_kernel<<<64, 1024>>>(ema_count, ema_weight, usage, out);
}